// round 9
// baseline (speedup 1.0000x reference)
#include <cuda_runtime.h>
#include <cuda_bf16.h>
#include <cstdint>

#define B_ 128
#define T_ 4096
#define F_ 64
#define H_ 128
#define G_ 512   /* 4*H */

// Scratch: precomputed input gates, PERMUTED layout, 1 GiB.
// For lstm thread t (256 thr, r=t>>1):
//   even t -> slot t   = i_r,  slot t+256 = f_r
//   odd  t -> slot t   = g_r,  slot t+256 = o_r
// i.e. perm slot t ties to original row jA(t), slot t+256 to jA(t)+128.
__device__ float g_xg[268435456ull];

// ---------------- f32x2 helpers (packed fp32: 2x FFMA throughput) ----------
__device__ __forceinline__ unsigned long long packf2(float x, float y) {
    unsigned long long r;
    asm("mov.b64 %0, {%1, %2};" : "=l"(r) : "f"(x), "f"(y));
    return r;
}
__device__ __forceinline__ float2 unpackf2(unsigned long long v) {
    float2 r;
    asm("mov.b64 {%0, %1}, %2;" : "=f"(r.x), "=f"(r.y) : "l"(v));
    return r;
}
__device__ __forceinline__ unsigned long long ffma2(unsigned long long a,
                                                    unsigned long long b,
                                                    unsigned long long c) {
    unsigned long long d;
    asm("fma.rn.f32x2 %0, %1, %2, %3;" : "=l"(d) : "l"(a), "l"(b), "l"(c));
    return d;
}

__device__ __forceinline__ float sigmoidf_(float x) {
    return __fdividef(1.0f, 1.0f + __expf(-x));
}
__device__ __forceinline__ float tanhf_(float x) {
    float ax = fabsf(x);
    float e  = __expf(-2.0f * ax);           // e in (0,1], never overflows
    float t  = __fdividef(1.0f - e, 1.0f + e);
    return copysignf(t, x);
}

// original gate row for permuted slot t (t in 0..255): even->i_r, odd->g_r
__device__ __host__ __forceinline__ int perm_rowA(int t) {
    int r = t >> 1;
    return (t & 1) ? (256 + r) : r;          // g_r : i_r   (B row = +128)
}

// ---------------------------------------------------------------------------
// Kernel 1: xg (input-gate precompute), writes permuted layout.
// grid (T/64, B), 256 threads. Thread t writes slots t (row jA) and
// t+256 (row jA+128).
// ---------------------------------------------------------------------------
__global__ __launch_bounds__(256) void xg_kernel(
    const float* __restrict__ X,
    const float* __restrict__ W_ih,
    const float* __restrict__ b_ih,
    const float* __restrict__ b_hh)
{
    extern __shared__ float smem[];
    float* sW = smem;                 // 512 x 65 (pad 1 -> conflict-free)
    float* sX = smem + 512 * 65;      // 64 x 64 (16B-aligned offset)

    const int t  = threadIdx.x;
    const int b  = blockIdx.y;
    const int t0 = blockIdx.x * 64;

    for (int idx = t; idx < 512 * 64; idx += 256) {
        int j = idx >> 6, k = idx & 63;
        sW[j * 65 + k] = W_ih[idx];
    }
    const float* Xb = X + ((size_t)b * T_ + t0) * F_;
    for (int idx = t; idx < 64 * 64; idx += 256) sX[idx] = Xb[idx];
    __syncthreads();

    const int jA = perm_rowA(t);
    const int jB = jA + 128;

    unsigned long long wpA[32], wpB[32];
#pragma unroll
    for (int p = 0; p < 32; ++p) {
        wpA[p] = packf2(sW[jA * 65 + 2 * p], sW[jA * 65 + 2 * p + 1]);
        wpB[p] = packf2(sW[jB * 65 + 2 * p], sW[jB * 65 + 2 * p + 1]);
    }
    const float biasA = __ldg(b_ih + jA) + __ldg(b_hh + jA);
    const float biasB = __ldg(b_ih + jB) + __ldg(b_hh + jB);

    float* outb = g_xg + ((size_t)b * T_ + t0) * G_;

    for (int tt = 0; tt < 64; ++tt) {
        const ulonglong2* x2 = (const ulonglong2*)(sX + tt * 64);
        unsigned long long aA0 = 0, aA1 = 0, aB0 = 0, aB1 = 0;
#pragma unroll
        for (int q = 0; q < 16; ++q) {
            ulonglong2 hq = x2[q];            // 4 floats, broadcast LDS.128
            aA0 = ffma2(wpA[2 * q],     hq.x, aA0);
            aA1 = ffma2(wpA[2 * q + 1], hq.y, aA1);
            aB0 = ffma2(wpB[2 * q],     hq.x, aB0);
            aB1 = ffma2(wpB[2 * q + 1], hq.y, aB1);
        }
        float2 u0 = unpackf2(aA0), u1 = unpackf2(aA1);
        float2 v0 = unpackf2(aB0), v1 = unpackf2(aB1);
        outb[(size_t)tt * G_ + t]       = (u0.x + u0.y) + (u1.x + u1.y) + biasA;
        outb[(size_t)tt * G_ + t + 256] = (v0.x + v0.y) + (v1.x + v1.y) + biasB;
    }
}

// ---------------------------------------------------------------------------
// Kernel 2: persistent LSTM. One CTA per batch row, 256 threads (8 warps,
// 255-reg cap). Thread t owns TWO gate rows (r = t>>1):
//   even t: (i_r, f_r), owns c_r      odd t: (g_r, o_r), owns h_r
// Weights: k=0..95 fp32 register-resident (96 u64 = 192 regs),
//          k=96..127 fp32 streamed from shared (16 LDS.128/thread,
//          64 KB/CTA/step). All fp32 -> rel_err ~3e-7, no unpack ALU.
// Epilogue: 2 shfl_xor(1), ONE __syncthreads/step, h double-buffered.
// ---------------------------------------------------------------------------
__global__ __launch_bounds__(256, 1) void lstm_kernel(
    const float* __restrict__ W_hh,
    float* __restrict__ out)
{
    extern __shared__ float dsm[];
    float* sh_h = dsm;                                // [2][128]
    ulonglong2* sws = (ulonglong2*)(dsm + 256);       // [16][256], 64 KB

    const int t = threadIdx.x;
    const int b = blockIdx.x;
    const int r = t >> 1;
    const bool odd = (t & 1) != 0;
    const int rowA = perm_rowA(t);                    // i_r or g_r
    const int rowB = rowA + 128;                      // f_r or o_r

    const float* WA = W_hh + (size_t)rowA * H_;
    const float* WB = W_hh + (size_t)rowB * H_;

    // k = 0..95 resident: 48 f32x2 pairs per row (192 regs total)
    unsigned long long wpA[48], wpB[48];
#pragma unroll
    for (int q = 0; q < 24; ++q) {
        float4 a = __ldg((const float4*)(WA + 4 * q));
        wpA[2 * q]     = packf2(a.x, a.y);
        wpA[2 * q + 1] = packf2(a.z, a.w);
        float4 c4 = __ldg((const float4*)(WB + 4 * q));
        wpB[2 * q]     = packf2(c4.x, c4.y);
        wpB[2 * q + 1] = packf2(c4.z, c4.w);
    }
    // k = 96..127 streamed, fp32, lane-major (conflict-free)
#pragma unroll
    for (int v = 0; v < 8; ++v) {
        float4 a  = __ldg((const float4*)(WA + 96 + 4 * v));
        float4 c4 = __ldg((const float4*)(WB + 96 + 4 * v));
        sws[v * 256 + t]       = *(const ulonglong2*)&a;
        sws[(8 + v) * 256 + t] = *(const ulonglong2*)&c4;
    }
    sh_h[t] = 0.0f;                                   // zero both h buffers
    __syncthreads();

    const float* px = g_xg + (size_t)b * T_ * G_ + t; // permuted, coalesced

    float c = 0.0f;
    float h_out = 0.0f;

    for (int ts = 0; ts < T_; ++ts) {
        // this step's xg, issued early, consumed ~150 instructions later
        float xgA = __ldg(px);
        float xgB = __ldg(px + 256);
        px += G_;

        const ulonglong2* hv = (const ulonglong2*)(sh_h + ((ts & 1) << 7));
        unsigned long long aA0 = 0, aA1 = 0, aB0 = 0, aB1 = 0;
#pragma unroll
        for (int q = 0; q < 24; ++q) {                // k=0..95, resident W
            ulonglong2 hq = hv[q];                    // broadcast LDS.128
            aA0 = ffma2(wpA[2 * q],     hq.x, aA0);
            aA1 = ffma2(wpA[2 * q + 1], hq.y, aA1);
            aB0 = ffma2(wpB[2 * q],     hq.x, aB0);
            aB1 = ffma2(wpB[2 * q + 1], hq.y, aB1);
        }
#pragma unroll
        for (int v = 0; v < 8; ++v) {                 // k=96..127, streamed W
            ulonglong2 hq = hv[24 + v];
            ulonglong2 wA = sws[v * 256 + t];
            ulonglong2 wB = sws[(8 + v) * 256 + t];
            aA0 = ffma2(wA.x, hq.x, aA0);
            aA1 = ffma2(wA.y, hq.y, aA1);
            aB0 = ffma2(wB.x, hq.x, aB0);
            aB1 = ffma2(wB.y, hq.y, aB1);
        }
        float2 u0 = unpackf2(aA0), u1 = unpackf2(aA1);
        float2 w0 = unpackf2(aB0), w1 = unpackf2(aB1);
        float gA = (u0.x + u0.y) + (u1.x + u1.y) + xgA;
        float gB = (w0.x + w0.y) + (w1.x + w1.y) + xgB;

        // even: a=sig(i), bb=sig(f)   odd: a=tanh(g), bb=sig(o)
        float a  = odd ? tanhf_(gA) : sigmoidf_(gA);
        float bb = sigmoidf_(gB);
        float aX = __shfl_xor_sync(0xFFFFFFFFu, a, 1);   // even gets tanh(g)
        float tc = 0.0f;
        if (!odd) {
            c = fmaf(bb, c, a * aX);                     // c = f*c + i*g
            tc = tanhf_(c);
        }
        float tcX = __shfl_xor_sync(0xFFFFFFFFu, tc, 1); // odd gets tanh(c)
        if (odd) {
            float h = bb * tcX;                          // h = o*tanh(c)
            sh_h[(((ts + 1) & 1) << 7) + r] = h;
            h_out = h;
        }

        __syncthreads();                                 // h visible next step
    }

    if (odd) out[(size_t)b * H_ + r] = h_out;
}

// ---------------------------------------------------------------------------
extern "C" void kernel_launch(void* const* d_in, const int* in_sizes, int n_in,
                              void* d_out, int out_size)
{
    const float* X    = (const float*)d_in[0];   // [128,4096,64]
    const float* W_ih = (const float*)d_in[1];   // [512,64]
    const float* W_hh = (const float*)d_in[2];   // [512,128]
    const float* b_ih = (const float*)d_in[3];   // [512]
    const float* b_hh = (const float*)d_in[4];   // [512]
    float* out = (float*)d_out;                  // [128,128]

    size_t smem1 = (size_t)(512 * 65 + 64 * 64) * sizeof(float);  // ~146 KB
    cudaFuncSetAttribute(xg_kernel,
                         cudaFuncAttributeMaxDynamicSharedMemorySize, (int)smem1);

    size_t smem2 = 256 * sizeof(float) + 16 * 256 * sizeof(ulonglong2); // 66.5 KB
    cudaFuncSetAttribute(lstm_kernel,
                         cudaFuncAttributeMaxDynamicSharedMemorySize, (int)smem2);

    dim3 g1(T_ / 64, B_);
    xg_kernel<<<g1, 256, smem1>>>(X, W_ih, b_ih, b_hh);
    lstm_kernel<<<B_, 256, smem2>>>(W_hh, out);
}

// round 12
// speedup vs baseline: 1.2299x; 1.2299x over previous
#include <cuda_runtime.h>
#include <cuda_bf16.h>
#include <cstdint>

#define B_ 128
#define T_ 4096
#define F_ 64
#define H_ 128
#define G_ 512   /* 4*H */

// Scratch: precomputed input gates, PERMUTED layout, 1 GiB.
// For lstm thread t (256 thr, r=t>>1):
//   even t -> slot t = i_r, slot t+256 = f_r
//   odd  t -> slot t = g_r, slot t+256 = o_r
__device__ float g_xg[268435456ull];

// ---------------- f32x2 helpers (packed fp32: 2x FFMA throughput) ----------
__device__ __forceinline__ unsigned long long packf2(float x, float y) {
    unsigned long long r;
    asm("mov.b64 %0, {%1, %2};" : "=l"(r) : "f"(x), "f"(y));
    return r;
}
__device__ __forceinline__ float2 unpackf2(unsigned long long v) {
    float2 r;
    asm("mov.b64 {%0, %1}, %2;" : "=f"(r.x), "=f"(r.y) : "l"(v));
    return r;
}
__device__ __forceinline__ unsigned long long ffma2(unsigned long long a,
                                                    unsigned long long b,
                                                    unsigned long long c) {
    unsigned long long d;
    asm("fma.rn.f32x2 %0, %1, %2, %3;" : "=l"(d) : "l"(a), "l"(b), "l"(c));
    return d;
}

// ACCURATE activations (proven 2.9e-7 end-to-end over T=4096).
__device__ __forceinline__ float sigmoidf_(float x) {
    return __fdividef(1.0f, 1.0f + __expf(-x));
}
__device__ __forceinline__ float tanhf_(float x) {
    float ax = fabsf(x);
    float e  = __expf(-2.0f * ax);           // e in (0,1], never overflows
    float t  = __fdividef(1.0f - e, 1.0f + e);
    return copysignf(t, x);
}

// original gate row for permuted slot t (t in 0..255): even->i_r, odd->g_r
__device__ __host__ __forceinline__ int perm_rowA(int t) {
    int r = t >> 1;
    return (t & 1) ? (256 + r) : r;          // g_r : i_r   (B row = +128)
}

// ---------------------------------------------------------------------------
// Kernel 1: xg (input-gate precompute), permuted output layout.
// grid (T/64, B), 256 threads.
// ---------------------------------------------------------------------------
__global__ __launch_bounds__(256) void xg_kernel(
    const float* __restrict__ X,
    const float* __restrict__ W_ih,
    const float* __restrict__ b_ih,
    const float* __restrict__ b_hh)
{
    extern __shared__ float smem[];
    float* sW = smem;                 // 512 x 65 (pad 1 -> conflict-free)
    float* sX = smem + 512 * 65;      // 64 x 64

    const int t  = threadIdx.x;
    const int b  = blockIdx.y;
    const int t0 = blockIdx.x * 64;

    for (int idx = t; idx < 512 * 64; idx += 256) {
        int j = idx >> 6, k = idx & 63;
        sW[j * 65 + k] = W_ih[idx];
    }
    const float* Xb = X + ((size_t)b * T_ + t0) * F_;
    for (int idx = t; idx < 64 * 64; idx += 256) sX[idx] = Xb[idx];
    __syncthreads();

    const int jA = perm_rowA(t);
    const int jB = jA + 128;

    unsigned long long wpA[32], wpB[32];
#pragma unroll
    for (int p = 0; p < 32; ++p) {
        wpA[p] = packf2(sW[jA * 65 + 2 * p], sW[jA * 65 + 2 * p + 1]);
        wpB[p] = packf2(sW[jB * 65 + 2 * p], sW[jB * 65 + 2 * p + 1]);
    }
    const float biasA = __ldg(b_ih + jA) + __ldg(b_hh + jA);
    const float biasB = __ldg(b_ih + jB) + __ldg(b_hh + jB);

    float* outb = g_xg + ((size_t)b * T_ + t0) * G_;

    for (int tt = 0; tt < 64; ++tt) {
        const ulonglong2* x2 = (const ulonglong2*)(sX + tt * 64);
        unsigned long long aA0 = 0, aA1 = 0, aB0 = 0, aB1 = 0;
#pragma unroll
        for (int q = 0; q < 16; ++q) {
            ulonglong2 hq = x2[q];            // broadcast LDS.128
            aA0 = ffma2(wpA[2 * q],     hq.x, aA0);
            aA1 = ffma2(wpA[2 * q + 1], hq.y, aA1);
            aB0 = ffma2(wpB[2 * q],     hq.x, aB0);
            aB1 = ffma2(wpB[2 * q + 1], hq.y, aB1);
        }
        float2 u0 = unpackf2(aA0), u1 = unpackf2(aA1);
        float2 v0 = unpackf2(aB0), v1 = unpackf2(aB1);
        outb[(size_t)tt * G_ + t]       = (u0.x + u0.y) + (u1.x + u1.y) + biasA;
        outb[(size_t)tt * G_ + t + 256] = (v0.x + v0.y) + (v1.x + v1.y) + biasB;
    }
}

// ---------------------------------------------------------------------------
// Kernel 2: persistent LSTM. One CTA per batch row, 256 threads (8 warps).
// Thread t owns TWO gate rows (r = t>>1):
//   even t: (i_r, f_r), owns c_r      odd t: (g_r, o_r), owns h_r
// Split (FULL k coverage — R9/R10 dropped k=96..127, rel_err 0.1):
//   k = 0..79  resident: 40 f32x2 pairs x 2 rows = 160 regs
//   k = 80..127 streamed: 12 ulonglong2 x 2 rows from shared each step
//     (96 KB/CTA/step ~ 768 crossbar cyc, overlapping the FMA pipe)
// ~50 free registers -> ptxas batches the 24 streamed LDS.128 + 12
// h-broadcast LDS.128 + 2 LDG deep into flight (R8 failure mode was 254
// regs / 0 free -> every load serialized its latency, issue=20.7%).
// ACCURATE __expf activations. One __syncthreads/step; h double-buffered.
// ---------------------------------------------------------------------------
__global__ __launch_bounds__(256, 1) void lstm_kernel(
    const float* __restrict__ W_hh,
    float* __restrict__ out)
{
    extern __shared__ float dsm[];
    float* sh_h = dsm;                                // [2][128]
    ulonglong2* sws = (ulonglong2*)(dsm + 256);       // [24][256], 96 KB

    const int t = threadIdx.x;
    const int b = blockIdx.x;
    const int r = t >> 1;
    const bool odd = (t & 1) != 0;
    const int rowA = perm_rowA(t);                    // i_r or g_r
    const int rowB = rowA + 128;                      // f_r or o_r

    const float* WA = W_hh + (size_t)rowA * H_;
    const float* WB = W_hh + (size_t)rowB * H_;

    // k = 0..79 resident: 40 f32x2 pairs per row (160 regs total)
    unsigned long long wpA[40], wpB[40];
#pragma unroll
    for (int q = 0; q < 20; ++q) {
        float4 a = __ldg((const float4*)(WA + 4 * q));
        wpA[2 * q]     = packf2(a.x, a.y);
        wpA[2 * q + 1] = packf2(a.z, a.w);
        float4 c4 = __ldg((const float4*)(WB + 4 * q));
        wpB[2 * q]     = packf2(c4.x, c4.y);
        wpB[2 * q + 1] = packf2(c4.z, c4.w);
    }
    // k = 80..127 streamed (12 float4 per row -> 48 floats = full coverage):
    // row A -> sws[0..11], row B -> sws[12..23], lane-major (conflict-free)
#pragma unroll
    for (int v = 0; v < 12; ++v) {
        float4 a  = __ldg((const float4*)(WA + 80 + 4 * v));
        float4 c4 = __ldg((const float4*)(WB + 80 + 4 * v));
        sws[v * 256 + t]        = *(const ulonglong2*)&a;
        sws[(12 + v) * 256 + t] = *(const ulonglong2*)&c4;
    }
    sh_h[t] = 0.0f;                                   // zero both h buffers
    __syncthreads();

    const float* px = g_xg + (size_t)b * T_ * G_ + t; // permuted, coalesced

    float c = 0.0f;
    float h_out = 0.0f;

    for (int ts = 0; ts < T_; ++ts) {
        // this step's xg, issued early (free regs -> stays in flight)
        float xgA = __ldg(px);
        float xgB = __ldg(px + 256);
        px += G_;

        const ulonglong2* hv = (const ulonglong2*)(sh_h + ((ts & 1) << 7));
        unsigned long long aA0 = 0, aA1 = 0, aB0 = 0, aB1 = 0;
#pragma unroll
        for (int q = 0; q < 20; ++q) {                // k=0..79, resident W
            ulonglong2 hq = hv[q];                    // broadcast LDS.128
            aA0 = ffma2(wpA[2 * q],     hq.x, aA0);
            aA1 = ffma2(wpA[2 * q + 1], hq.y, aA1);
            aB0 = ffma2(wpB[2 * q],     hq.x, aB0);
            aB1 = ffma2(wpB[2 * q + 1], hq.y, aB1);
        }
#pragma unroll
        for (int v = 0; v < 12; ++v) {                // k=80..127, streamed W
            ulonglong2 hq = hv[20 + v];               // h[80..127]
            ulonglong2 wA = sws[v * 256 + t];
            ulonglong2 wB = sws[(12 + v) * 256 + t];
            aA0 = ffma2(wA.x, hq.x, aA0);
            aA1 = ffma2(wA.y, hq.y, aA1);
            aB0 = ffma2(wB.x, hq.x, aB0);
            aB1 = ffma2(wB.y, hq.y, aB1);
        }
        float2 u0 = unpackf2(aA0), u1 = unpackf2(aA1);
        float2 w0 = unpackf2(aB0), w1 = unpackf2(aB1);
        float gA = (u0.x + u0.y) + (u1.x + u1.y) + xgA;
        float gB = (w0.x + w0.y) + (w1.x + w1.y) + xgB;

        // even: a=sig(i), bb=sig(f)   odd: a=tanh(g), bb=sig(o)
        float a  = odd ? tanhf_(gA) : sigmoidf_(gA);
        float bb = sigmoidf_(gB);
        float aX = __shfl_xor_sync(0xFFFFFFFFu, a, 1);   // even gets tanh(g)
        float tc = 0.0f;
        if (!odd) {
            c = fmaf(bb, c, a * aX);                     // c = f*c + i*g
            tc = tanhf_(c);
        }
        float tcX = __shfl_xor_sync(0xFFFFFFFFu, tc, 1); // odd gets tanh(c)
        if (odd) {
            float h = bb * tcX;                          // h = o*tanh(c)
            sh_h[(((ts + 1) & 1) << 7) + r] = h;
            h_out = h;
        }

        __syncthreads();                                 // h visible next step
    }

    if (odd) out[(size_t)b * H_ + r] = h_out;
}

// ---------------------------------------------------------------------------
extern "C" void kernel_launch(void* const* d_in, const int* in_sizes, int n_in,
                              void* d_out, int out_size)
{
    const float* X    = (const float*)d_in[0];   // [128,4096,64]
    const float* W_ih = (const float*)d_in[1];   // [512,64]
    const float* W_hh = (const float*)d_in[2];   // [512,128]
    const float* b_ih = (const float*)d_in[3];   // [512]
    const float* b_hh = (const float*)d_in[4];   // [512]
    float* out = (float*)d_out;                  // [128,128]

    size_t smem1 = (size_t)(512 * 65 + 64 * 64) * sizeof(float);  // ~146 KB
    cudaFuncSetAttribute(xg_kernel,
                         cudaFuncAttributeMaxDynamicSharedMemorySize, (int)smem1);

    size_t smem2 = 256 * sizeof(float) + 24 * 256 * sizeof(ulonglong2); // ~97 KB
    cudaFuncSetAttribute(lstm_kernel,
                         cudaFuncAttributeMaxDynamicSharedMemorySize, (int)smem2);

    dim3 g1(T_ / 64, B_);
    xg_kernel<<<g1, 256, smem1>>>(X, W_ih, b_ih, b_hh);
    lstm_kernel<<<B_, 256, smem2>>>(W_hh, out);
}

// round 14
// speedup vs baseline: 1.3648x; 1.1096x over previous
#include <cuda_runtime.h>
#include <cuda_bf16.h>
#include <cstdint>

#define B_ 128
#define T_ 4096
#define F_ 64
#define H_ 128
#define G_ 512   /* 4*H */

// Scratch: precomputed input gates, PERMUTED + PAIRED layout, 1 GiB.
// lstm thread t (256 thr, r=t>>1) reads ONE float2 at slot pair (2t, 2t+1):
//   slot 2t   = xg of rowA(t)   (even t: i_r, odd t: g_r)
//   slot 2t+1 = xg of rowB(t)   (even t: f_r, odd t: o_r)
__device__ float g_xg[268435456ull];

// ---------------- f32x2 helpers (packed fp32: 2x FFMA throughput) ----------
__device__ __forceinline__ unsigned long long packf2(float x, float y) {
    unsigned long long r;
    asm("mov.b64 %0, {%1, %2};" : "=l"(r) : "f"(x), "f"(y));
    return r;
}
__device__ __forceinline__ float2 unpackf2(unsigned long long v) {
    float2 r;
    asm("mov.b64 {%0, %1}, %2;" : "=f"(r.x), "=f"(r.y) : "l"(v));
    return r;
}
__device__ __forceinline__ unsigned long long ffma2(unsigned long long a,
                                                    unsigned long long b,
                                                    unsigned long long c) {
    unsigned long long d;
    asm("fma.rn.f32x2 %0, %1, %2, %3;" : "=l"(d) : "l"(a), "l"(b), "l"(c));
    return d;
}
// bf16x2 (u32, low=first) -> f32x2 (u64). Pure ALU-pipe: SHL + LOP + pack.
__device__ __forceinline__ unsigned long long bf2tof2(unsigned int u) {
    unsigned int lo = u << 16;
    unsigned int hi = u & 0xFFFF0000u;
    unsigned long long r;
    asm("mov.b64 %0, {%1, %2};" : "=l"(r) : "r"(lo), "r"(hi));
    return r;
}
__device__ __forceinline__ unsigned int packbf(float x, float y) {
    unsigned short sx = __bfloat16_as_ushort(__float2bfloat16(x));
    unsigned short sy = __bfloat16_as_ushort(__float2bfloat16(y));
    return ((unsigned)sy << 16) | (unsigned)sx;
}

// ACCURATE activations (proven 2.9e-7; approx diverges over T=4096).
__device__ __forceinline__ float sigmoidf_(float x) {
    return __fdividef(1.0f, 1.0f + __expf(-x));
}
__device__ __forceinline__ float tanhf_(float x) {
    float ax = fabsf(x);
    float e  = __expf(-2.0f * ax);
    float t  = __fdividef(1.0f - e, 1.0f + e);
    return copysignf(t, x);
}

// original gate row for slot pair of thread t: even->i_r, odd->g_r (B=+128)
__device__ __host__ __forceinline__ int perm_rowA(int t) {
    int r = t >> 1;
    return (t & 1) ? (256 + r) : r;
}

// ---------------------------------------------------------------------------
// Kernel 1: xg precompute. grid (T/64, B), 256 threads.
// Thread t produces rows jA=perm_rowA(t), jB=jA+128 and stores them PAIRED
// at float slots (2t, 2t+1) -> one STG.64, and the lstm reads one LDG.64.
// ---------------------------------------------------------------------------
__global__ __launch_bounds__(256) void xg_kernel(
    const float* __restrict__ X,
    const float* __restrict__ W_ih,
    const float* __restrict__ b_ih,
    const float* __restrict__ b_hh)
{
    extern __shared__ float smem[];
    float* sW = smem;                 // 512 x 65 (pad 1 -> conflict-free)
    float* sX = smem + 512 * 65;      // 64 x 64

    const int t  = threadIdx.x;
    const int b  = blockIdx.y;
    const int t0 = blockIdx.x * 64;

    for (int idx = t; idx < 512 * 64; idx += 256) {
        int j = idx >> 6, k = idx & 63;
        sW[j * 65 + k] = W_ih[idx];
    }
    const float* Xb = X + ((size_t)b * T_ + t0) * F_;
    for (int idx = t; idx < 64 * 64; idx += 256) sX[idx] = Xb[idx];
    __syncthreads();

    const int jA = perm_rowA(t);
    const int jB = jA + 128;

    unsigned long long wpA[32], wpB[32];
#pragma unroll
    for (int p = 0; p < 32; ++p) {
        wpA[p] = packf2(sW[jA * 65 + 2 * p], sW[jA * 65 + 2 * p + 1]);
        wpB[p] = packf2(sW[jB * 65 + 2 * p], sW[jB * 65 + 2 * p + 1]);
    }
    const float biasA = __ldg(b_ih + jA) + __ldg(b_hh + jA);
    const float biasB = __ldg(b_ih + jB) + __ldg(b_hh + jB);

    float2* outb = (float2*)(g_xg + ((size_t)b * T_ + t0) * G_) + t;

    for (int tt = 0; tt < 64; ++tt) {
        const ulonglong2* x2 = (const ulonglong2*)(sX + tt * 64);
        unsigned long long aA0 = 0, aA1 = 0, aB0 = 0, aB1 = 0;
#pragma unroll
        for (int q = 0; q < 16; ++q) {
            ulonglong2 hq = x2[q];            // broadcast LDS.128
            aA0 = ffma2(wpA[2 * q],     hq.x, aA0);
            aA1 = ffma2(wpA[2 * q + 1], hq.y, aA1);
            aB0 = ffma2(wpB[2 * q],     hq.x, aB0);
            aB1 = ffma2(wpB[2 * q + 1], hq.y, aB1);
        }
        float2 u0 = unpackf2(aA0), u1 = unpackf2(aA1);
        float2 v0 = unpackf2(aB0), v1 = unpackf2(aB1);
        float2 o;
        o.x = (u0.x + u0.y) + (u1.x + u1.y) + biasA;
        o.y = (v0.x + v0.y) + (v1.x + v1.y) + biasB;
        outb[(size_t)tt * 256] = o;           // STG.64, coalesced
    }
}

// ---------------------------------------------------------------------------
// Kernel 2: persistent LSTM. One CTA per batch row, 256 threads (8 warps).
// Thread t owns TWO gate rows (r = t>>1):
//   even t: (i_r, f_r), owns c_r      odd t: (g_r, o_r), owns h_r
// Weight split = R1's measured-best (crossbar traffic is the bottleneck):
//   k = 0..95  : fp32 register-resident (96 u64 = 192 regs)
//   k = 96..127: bf16 streamed from shared — 2 uint4 LDS.128/thread/step
//                (16 KB/CTA/step vs 96 KB fp32); unpack on the idle ALU pipe.
// Next-step xg prefetch: __ldg(pf + inc), inc=0 on the LAST step (the R12
// version advanced the pointer past the array end for b=127 -> OOB fault).
// One __syncthreads/step; shfl_xor epilogue; h double-buffered.
// ---------------------------------------------------------------------------
__global__ __launch_bounds__(256, 1) void lstm_kernel(
    const float* __restrict__ W_hh,
    float* __restrict__ out)
{
    __shared__ alignas(16) float sh_h[2][128];    // 1 KB
    __shared__ uint4 sws[8][256];                 // 32 KB, bf16 streamed W

    const int t = threadIdx.x;
    const int b = blockIdx.x;
    const int r = t >> 1;
    const bool odd = (t & 1) != 0;
    const int rowA = perm_rowA(t);                // i_r or g_r
    const int rowB = rowA + 128;                  // f_r or o_r

    const float* WA = W_hh + (size_t)rowA * H_;
    const float* WB = W_hh + (size_t)rowB * H_;

    // k = 0..95 resident: 48 f32x2 pairs per row (192 regs)
    unsigned long long wpA[48], wpB[48];
#pragma unroll
    for (int q = 0; q < 24; ++q) {
        float4 a = __ldg((const float4*)(WA + 4 * q));
        wpA[2 * q]     = packf2(a.x, a.y);
        wpA[2 * q + 1] = packf2(a.z, a.w);
        float4 c4 = __ldg((const float4*)(WB + 4 * q));
        wpB[2 * q]     = packf2(c4.x, c4.y);
        wpB[2 * q + 1] = packf2(c4.z, c4.w);
    }
    // k = 96..127 as packed bf16: 4 uint4 per row, lane-major
#pragma unroll
    for (int v = 0; v < 4; ++v) {
        float4 a0 = __ldg((const float4*)(WA + 96 + 8 * v));
        float4 a1 = __ldg((const float4*)(WA + 100 + 8 * v));
        sws[v][t] = make_uint4(packbf(a0.x, a0.y), packbf(a0.z, a0.w),
                               packbf(a1.x, a1.y), packbf(a1.z, a1.w));
        float4 b0 = __ldg((const float4*)(WB + 96 + 8 * v));
        float4 b1 = __ldg((const float4*)(WB + 100 + 8 * v));
        sws[4 + v][t] = make_uint4(packbf(b0.x, b0.y), packbf(b0.z, b0.w),
                                   packbf(b1.x, b1.y), packbf(b1.z, b1.w));
    }
    if (t < 128) { sh_h[0][t] = 0.0f; sh_h[1][t] = 0.0f; }
    __syncthreads();

    const float2* pf = (const float2*)(g_xg + (size_t)b * T_ * G_) + t;
    float2 xgc = __ldg(pf);                       // step 0's xg

    float c = 0.0f;
    float h_out = 0.0f;

    for (int ts = 0; ts < T_; ++ts) {
        // prefetch NEXT step's xg; inc=0 on the last step (stays in bounds)
        const int inc = (ts < T_ - 1) ? 256 : 0;
        float2 nx = __ldg(pf + inc);

        const ulonglong2* hv = (const ulonglong2*)sh_h[ts & 1];
        unsigned long long aA0 = 0, aA1 = 0, aB0 = 0, aB1 = 0;
#pragma unroll
        for (int q = 0; q < 24; ++q) {            // k=0..95, resident fp32
            ulonglong2 hq = hv[q];                // broadcast LDS.128
            aA0 = ffma2(wpA[2 * q],     hq.x, aA0);
            aA1 = ffma2(wpA[2 * q + 1], hq.y, aA1);
            aB0 = ffma2(wpB[2 * q],     hq.x, aB0);
            aB1 = ffma2(wpB[2 * q + 1], hq.y, aB1);
        }
#pragma unroll
        for (int v = 0; v < 4; ++v) {             // k=96..127, streamed bf16
            uint4 ua = sws[v][t];
            uint4 ub = sws[4 + v][t];
            ulonglong2 h0 = hv[24 + 2 * v];
            ulonglong2 h1 = hv[25 + 2 * v];
            aA0 = ffma2(bf2tof2(ua.x), h0.x, aA0);
            aA1 = ffma2(bf2tof2(ua.y), h0.y, aA1);
            aA0 = ffma2(bf2tof2(ua.z), h1.x, aA0);
            aA1 = ffma2(bf2tof2(ua.w), h1.y, aA1);
            aB0 = ffma2(bf2tof2(ub.x), h0.x, aB0);
            aB1 = ffma2(bf2tof2(ub.y), h0.y, aB1);
            aB0 = ffma2(bf2tof2(ub.z), h1.x, aB0);
            aB1 = ffma2(bf2tof2(ub.w), h1.y, aB1);
        }
        float2 u0 = unpackf2(aA0), u1 = unpackf2(aA1);
        float2 w0 = unpackf2(aB0), w1 = unpackf2(aB1);
        float gA = (u0.x + u0.y) + (u1.x + u1.y) + xgc.x;
        float gB = (w0.x + w0.y) + (w1.x + w1.y) + xgc.y;

        // even: a=sig(i), bb=sig(f)   odd: a=tanh(g), bb=sig(o)
        float a  = odd ? tanhf_(gA) : sigmoidf_(gA);
        float bb = sigmoidf_(gB);
        float aX = __shfl_xor_sync(0xFFFFFFFFu, a, 1);   // even gets tanh(g)
        float tc = 0.0f;
        if (!odd) {
            c = fmaf(bb, c, a * aX);                     // c = f*c + i*g
            tc = tanhf_(c);
        }
        float tcX = __shfl_xor_sync(0xFFFFFFFFu, tc, 1); // odd gets tanh(c)
        if (odd) {
            float h = bb * tcX;                          // h = o*tanh(c)
            sh_h[(ts + 1) & 1][r] = h;
            h_out = h;
        }

        xgc = nx; pf += inc;
        __syncthreads();                                 // h visible next step
    }

    if (odd) out[(size_t)b * H_ + r] = h_out;
}

// ---------------------------------------------------------------------------
extern "C" void kernel_launch(void* const* d_in, const int* in_sizes, int n_in,
                              void* d_out, int out_size)
{
    const float* X    = (const float*)d_in[0];   // [128,4096,64]
    const float* W_ih = (const float*)d_in[1];   // [512,64]
    const float* W_hh = (const float*)d_in[2];   // [512,128]
    const float* b_ih = (const float*)d_in[3];   // [512]
    const float* b_hh = (const float*)d_in[4];   // [512]
    float* out = (float*)d_out;                  // [128,128]

    size_t smem1 = (size_t)(512 * 65 + 64 * 64) * sizeof(float);  // ~146 KB
    cudaFuncSetAttribute(xg_kernel,
                         cudaFuncAttributeMaxDynamicSharedMemorySize, (int)smem1);

    dim3 g1(T_ / 64, B_);
    xg_kernel<<<g1, 256, smem1>>>(X, W_ih, b_ih, b_hh);
    lstm_kernel<<<B_, 256>>>(W_hh, out);
}